// round 16
// baseline (speedup 1.0000x reference)
#include <cuda_runtime.h>
#include <cuda_bf16.h>
#include <cuda_fp16.h>
#include <cstdint>

// Problem constants (fixed by setup_inputs)
#define MAXN 100000
#define MAXE 3200000
#define FIN  512
#define H1DIM 64   // 8 heads x 8 ch
#define HEADS 8
#define NCLS 16
#define MAXT (MAXE + MAXN)
#define SCAN_BS 1024
#define MAXB ((MAXN + SCAN_BS - 1) / SCAN_BS)

// ---------------- scratch (device globals; no allocations allowed) --------
__device__ __align__(16) __half  g_h1h[MAXN * H1DIM];    // x @ W1 (fp16, gather src)
__device__ __align__(16) __half  g_h2h[MAXN * NCLS];     // layer2 input rows (fp16)
__device__ __align__(16) __half2 g_as1e[MAXN * HEADS];   // {e^as, e^0.2as} fp16
__device__ __align__(16) __half2 g_ad1e[MAXN * HEADS];
__device__ __align__(16) __half2 g_as2e[MAXN];
__device__ __align__(16) __half2 g_ad2e[MAXN];
__device__ __align__(16) int g_csr[MAXT];                // src sorted by dst
__device__ int g_deg[MAXN];
__device__ int g_off[MAXN];
__device__ int g_cursor[MAXN];
__device__ int g_bsum[MAXB + 1];
__device__ int g_bflag[MAXB + 1];
__device__ int g_is64;

__device__ __forceinline__ uint32_t sptr(const void* p) {
    return (uint32_t)__cvta_generic_to_shared(p);
}
__device__ __forceinline__ void ldsm4(uint32_t* r, uint32_t a) {
    asm volatile("ldmatrix.sync.aligned.m8n8.x4.shared.b16 {%0,%1,%2,%3}, [%4];"
        : "=r"(r[0]), "=r"(r[1]), "=r"(r[2]), "=r"(r[3]) : "r"(a));
}
__device__ __forceinline__ void ldsm4t(uint32_t* r, uint32_t a) {
    asm volatile("ldmatrix.sync.aligned.m8n8.x4.trans.shared.b16 {%0,%1,%2,%3}, [%4];"
        : "=r"(r[0]), "=r"(r[1]), "=r"(r[2]), "=r"(r[3]) : "r"(a));
}
__device__ __forceinline__ void mma_bf16(float* c, const uint32_t* a, const uint32_t* b) {
    asm volatile(
        "mma.sync.aligned.m16n8k16.row.col.f32.bf16.bf16.f32 "
        "{%0,%1,%2,%3}, {%4,%5,%6,%7}, {%8,%9}, {%0,%1,%2,%3};"
        : "+f"(c[0]), "+f"(c[1]), "+f"(c[2]), "+f"(c[3])
        : "r"(a[0]), "r"(a[1]), "r"(a[2]), "r"(a[3]), "r"(b[0]), "r"(b[1]));
}
__device__ __forceinline__ unsigned int b2u(__nv_bfloat16 a, __nv_bfloat16 b) {
    unsigned short ua = *(unsigned short*)&a, ub = *(unsigned short*)&b;
    return ((unsigned)ub << 16) | (unsigned)ua;
}
__device__ __forceinline__ float qreduce(float v) {   // sum over quad (lanes ^1, ^2)
    v += __shfl_xor_sync(0xFFFFFFFF, v, 1);
    v += __shfl_xor_sync(0xFFFFFFFF, v, 2);
    return v;
}

// decode edge e (0..T-1): src/dst with self-loops appended
__device__ __forceinline__ int edge_dst(const void* ei, int e, int E) {
    if (e >= E) return e - E;
    return g_is64 ? (int)((const long long*)ei)[(size_t)E + e]
                  : ((const int*)ei)[E + e];
}
__device__ __forceinline__ int edge_src(const void* ei, int e, int E) {
    if (e >= E) return e - E;
    return g_is64 ? (int)((const long long*)ei)[e]
                  : ((const int*)ei)[e];
}

// ---------------- setup: dtype detect + zero histogram & scan flags --------
__global__ void setup_kernel(const int* __restrict__ ei32, int N) {
    if (blockIdx.x == 0 && threadIdx.x < 32) {
        unsigned ballot = __ballot_sync(0xFFFFFFFF, ei32[2 * threadIdx.x + 1] != 0);
        if (threadIdx.x == 0) g_is64 = (ballot == 0u) ? 1 : 0;
    }
    int i = blockIdx.x * blockDim.x + threadIdx.x;
    if (i < N) g_deg[i] = 0;
    if (i <= MAXB) g_bflag[i] = 0;
}

// ---------------- histogram over dst (reads edge_index directly) ----------
__global__ void hist_kernel(const void* __restrict__ ei, int E, int N) {
    int e = blockIdx.x * blockDim.x + threadIdx.x;
    if (e >= E + N) return;
    atomicAdd(&g_deg[edge_dst(ei, e, E)], 1);
}

// ---------------- single-kernel scan with decoupled lookback ---------------
// 98 blocks x 1024 threads; all blocks co-resident (148 SMs) => spins are safe.
__global__ void scan_kernel(int N) {
    __shared__ int s[SCAN_BS];
    __shared__ int base_sh;
    int tid = threadIdx.x;
    int b   = blockIdx.x;
    int i   = b * SCAN_BS + tid;
    int v = (i < N) ? g_deg[i] : 0;
    s[tid] = v;
    __syncthreads();
    for (int o = 1; o < SCAN_BS; o <<= 1) {
        int t = (tid >= o) ? s[tid - o] : 0;
        __syncthreads();
        s[tid] += t;
        __syncthreads();
    }
    if (tid == 0) {
        g_bsum[b] = s[SCAN_BS - 1];
        __threadfence();
        atomicExch(&g_bflag[b], 1);
        base_sh = 0;
    }
    __syncthreads();
    if (tid < b) {   // b <= 97 < 1024: one predecessor per thread, parallel
        while (atomicAdd(&g_bflag[tid], 0) == 0) {}
        atomicAdd(&base_sh, __ldcg(&g_bsum[tid]));
    }
    __syncthreads();
    if (i < N) {
        int off = base_sh + s[tid] - v;   // exclusive prefix
        g_off[i] = off;
        g_cursor[i] = off;
    }
}

// ---------------- scatter edges into CSR by dst (reads edge_index) --------
__global__ void scatter_kernel(const void* __restrict__ ei, int E, int N) {
    int e = blockIdx.x * blockDim.x + threadIdx.x;
    if (e >= E + N) return;
    int dst = edge_dst(ei, e, E);
    int slot = atomicAdd(&g_cursor[dst], 1);
    g_csr[slot] = edge_src(ei, e, E);
}
// after scatter: g_cursor[d] == g_off[d] + deg[d] == row end

// ---------------- GEMM1 (tensor core, split-bf16, sw-pipelined) -----------
#define GBM 128
#define ASTR 40     // A smem row stride (bf16)
#define BSTR 72     // B smem row stride (bf16)

__device__ __forceinline__ void g1_load_a(const float* __restrict__ x, int m0, int M,
                                          int k0, int tid, float4* ra) {
#pragma unroll
    for (int it = 0; it < 2; it++)
#pragma unroll
        for (int pass = 0; pass < 4; pass++) {
            int row = pass * 32 + (tid >> 2);
            int c4  = (tid & 3) + it * 4;
            int gr  = m0 + row;
            float4 v = make_float4(0.f, 0.f, 0.f, 0.f);
            if (gr < M) v = *(const float4*)(x + (size_t)gr * FIN + k0 + c4 * 4);
            ra[it * 4 + pass] = v;
        }
}
__device__ __forceinline__ void g1_load_b(const float* __restrict__ W1, int k0,
                                          int tid, float4* rb) {
#pragma unroll
    for (int p = 0; p < 4; p++) {
        int t  = tid + p * 128;
        int kr = t >> 4;
        int c4 = t & 15;
        rb[p] = *(const float4*)(W1 + (size_t)(k0 + kr) * 64 + c4 * 4);
    }
}

__global__ __launch_bounds__(128) void gemm1_kernel(const float* __restrict__ x,
                                                    const float* __restrict__ W1,
                                                    const float* __restrict__ att_src,
                                                    const float* __restrict__ att_dst,
                                                    int M) {
    __shared__ __align__(16) __nv_bfloat16 Ah[GBM][ASTR];
    __shared__ __align__(16) __nv_bfloat16 Al[GBM][ASTR];
    __shared__ __align__(16) __nv_bfloat16 Bh[32][BSTR];   // [k][n]
    __shared__ __align__(16) __nv_bfloat16 Bl[32][BSTR];
    __shared__ float s_as[H1DIM], s_ad[H1DIM];
    int tid  = threadIdx.x;
    int lane = tid & 31;
    int wid  = tid >> 5;
    int m0   = blockIdx.x * GBM;
    int q    = lane & 3;
    int g    = lane >> 2;

    if (tid < H1DIM) { s_as[tid] = att_src[tid]; s_ad[tid] = att_dst[tid]; }

    float acc[2][8][4];
#pragma unroll
    for (int mt = 0; mt < 2; mt++)
#pragma unroll
        for (int nt = 0; nt < 8; nt++)
#pragma unroll
            for (int j = 0; j < 4; j++) acc[mt][nt][j] = 0.f;

    float4 ra[8], rb[4];
    g1_load_a(x, m0, M, 0, tid, ra);
    g1_load_b(W1, 0, tid, rb);

    for (int k0 = 0; k0 < FIN; k0 += 32) {
        // --- convert + store current chunk regs -> smem (hi/lo split)
#pragma unroll
        for (int it = 0; it < 2; it++)
#pragma unroll
            for (int pass = 0; pass < 4; pass++) {
                int row = pass * 32 + (tid >> 2);
                int c4  = (tid & 3) + it * 4;
                float4 v = ra[it * 4 + pass];
                float vv[4] = {v.x, v.y, v.z, v.w};
                __nv_bfloat16 hb[4], lb[4];
#pragma unroll
                for (int j = 0; j < 4; j++) {
                    hb[j] = __float2bfloat16(vv[j]);
                    lb[j] = __float2bfloat16(vv[j] - __bfloat162float(hb[j]));
                }
                *(uint2*)&Ah[row][c4 * 4] = make_uint2(b2u(hb[0], hb[1]), b2u(hb[2], hb[3]));
                *(uint2*)&Al[row][c4 * 4] = make_uint2(b2u(lb[0], lb[1]), b2u(lb[2], lb[3]));
            }
#pragma unroll
        for (int p = 0; p < 4; p++) {
            int t  = tid + p * 128;
            int kr = t >> 4;
            int c4 = t & 15;
            float4 v = rb[p];
            float vv[4] = {v.x, v.y, v.z, v.w};
            __nv_bfloat16 hb[4], lb[4];
#pragma unroll
            for (int j = 0; j < 4; j++) {
                hb[j] = __float2bfloat16(vv[j]);
                lb[j] = __float2bfloat16(vv[j] - __bfloat162float(hb[j]));
            }
            *(uint2*)&Bh[kr][c4 * 4] = make_uint2(b2u(hb[0], hb[1]), b2u(hb[2], hb[3]));
            *(uint2*)&Bl[kr][c4 * 4] = make_uint2(b2u(lb[0], lb[1]), b2u(lb[2], lb[3]));
        }
        __syncthreads();

        // --- prefetch next chunk into regs (latency hidden under mma below)
        if (k0 + 32 < FIN) {
            g1_load_a(x, m0, M, k0 + 32, tid, ra);
            g1_load_b(W1, k0 + 32, tid, rb);
        }

        // --- mma from smem
#pragma unroll
        for (int k16 = 0; k16 < 2; k16++) {
            int kkB = k16 * 16;
            uint32_t ah[2][4], al[2][4];
            int arow = lane & 15;
            int akk  = kkB + ((lane & 16) ? 8 : 0);
#pragma unroll
            for (int mt = 0; mt < 2; mt++) {
                ldsm4(ah[mt], sptr(&Ah[wid * 32 + mt * 16 + arow][akk]));
                ldsm4(al[mt], sptr(&Al[wid * 32 + mt * 16 + arow][akk]));
            }
#pragma unroll
            for (int p = 0; p < 4; p++) {
                int bk = kkB + (lane & 7) + ((lane & 8) ? 8 : 0);
                int bn = p * 16 + ((lane & 16) ? 8 : 0);
                uint32_t bh[4], bl[4];
                ldsm4t(bh, sptr(&Bh[bk][bn]));
                ldsm4t(bl, sptr(&Bl[bk][bn]));
#pragma unroll
                for (int mt = 0; mt < 2; mt++) {
                    mma_bf16(acc[mt][2 * p],     ah[mt], bh);
                    mma_bf16(acc[mt][2 * p],     al[mt], bh);
                    mma_bf16(acc[mt][2 * p],     ah[mt], bl);
                    mma_bf16(acc[mt][2 * p + 1], ah[mt], bh + 2);
                    mma_bf16(acc[mt][2 * p + 1], al[mt], bh + 2);
                    mma_bf16(acc[mt][2 * p + 1], ah[mt], bl + 2);
                }
            }
        }
        __syncthreads();
    }

    // --- epilogue: fp16 h1 + fused per-head attention exp tables (fp16)
#pragma unroll
    for (int mt = 0; mt < 2; mt++) {
        int row0 = m0 + wid * 32 + mt * 16 + g;
        int row1 = row0 + 8;
#pragma unroll
        for (int nt = 0; nt < 8; nt++) {
            int col = nt * 8 + q * 2;
            if (row0 < M)
                *(__half2*)(g_h1h + (size_t)row0 * H1DIM + col) =
                    __floats2half2_rn(acc[mt][nt][0], acc[mt][nt][1]);
            if (row1 < M)
                *(__half2*)(g_h1h + (size_t)row1 * H1DIM + col) =
                    __floats2half2_rn(acc[mt][nt][2], acc[mt][nt][3]);
            // attention dots for head nt (cols nt*8..nt*8+7), fp32
            float sa0 = s_as[col], sa1 = s_as[col + 1];
            float sd0 = s_ad[col], sd1 = s_ad[col + 1];
            float pas0 = qreduce(acc[mt][nt][0] * sa0 + acc[mt][nt][1] * sa1);
            float pad0 = qreduce(acc[mt][nt][0] * sd0 + acc[mt][nt][1] * sd1);
            float pas1 = qreduce(acc[mt][nt][2] * sa0 + acc[mt][nt][3] * sa1);
            float pad1 = qreduce(acc[mt][nt][2] * sd0 + acc[mt][nt][3] * sd1);
            float v   = (q == 0) ? pas0 : (q == 1) ? pad0 : (q == 2) ? pas1 : pad1;
            int   row = (q < 2) ? row0 : row1;
            __half2* tab = (q & 1) ? g_ad1e : g_as1e;
            if (row < M)
                tab[(size_t)row * HEADS + nt] = __floats2half2_rn(__expf(v), __expf(0.2f * v));
        }
    }
}

// ---------------- layer 1 gather FUSED with GEMM2 + attn2 tables ----------
// 8 threads/dst gather+normalize their 8 channels, apply bias+elu, compute
// the 16-wide @W2 partials, shfl-reduce across the 8 lanes, write fp16 h2
// and layer-2 attention exp tables. No g_out1, no separate gemm2 kernel.
__global__ __launch_bounds__(256) void gather1_kernel(int N,
        const float* __restrict__ W2, const float* __restrict__ att_src2,
        const float* __restrict__ att_dst2, const float* __restrict__ b1) {
    __shared__ float W2s[H1DIM * NCLS];
    __shared__ float s2[NCLS], d2[NCLS], b1s[H1DIM];
    int tid = threadIdx.x;
    for (int i = tid; i < H1DIM * NCLS; i += 256) W2s[i] = W2[i];
    if (tid < NCLS) { s2[tid] = att_src2[tid]; d2[tid] = att_dst2[tid]; }
    if (tid < H1DIM) b1s[tid] = b1[tid];
    __syncthreads();

    int gid = blockIdx.x * 256 + tid;
    int dst = gid >> 3;
    int h   = gid & 7;
    if (dst >= N) dst = N - 1;   // duplicates an existing (dst,h): identical writes

    float2 da = __half22float2(g_ad1e[(size_t)dst * HEADS + h]);
    int beg = g_off[dst];
    int end = g_cursor[dst];
    float4 a0 = make_float4(0.f, 0.f, 0.f, 0.f);
    float4 a1 = make_float4(0.f, 0.f, 0.f, 0.f);
    float denom = 0.f;
    // software pipeline: current edge's operands preloaded
    int src = g_csr[beg];
    __half2 sah = g_as1e[(size_t)src * HEADS + h];
    uint4 u = *(const uint4*)(g_h1h + (size_t)src * H1DIM + h * 8);
    for (int i = beg; i < end; i++) {
        int nsrc = (i + 1 < end) ? g_csr[i + 1] : src;
        __half2 nsah = g_as1e[(size_t)nsrc * HEADS + h];
        uint4 nu = *(const uint4*)(g_h1h + (size_t)nsrc * H1DIM + h * 8);
        float2 sa = __half22float2(sah);
        float w = fmaxf(sa.x * da.x, sa.y * da.y);   // e^lrelu(as+ad)
        float2 p0 = __half22float2(*(__half2*)&u.x);
        float2 p1 = __half22float2(*(__half2*)&u.y);
        float2 p2 = __half22float2(*(__half2*)&u.z);
        float2 p3 = __half22float2(*(__half2*)&u.w);
        a0.x += w * p0.x; a0.y += w * p0.y; a0.z += w * p1.x; a0.w += w * p1.y;
        a1.x += w * p2.x; a1.y += w * p2.y; a1.z += w * p3.x; a1.w += w * p3.y;
        denom += w;
        sah = nsah; u = nu; src = nsrc;
    }
    float inv = 1.f / denom;

    // normalized row slice -> bias + elu
    float val[8] = {a0.x * inv, a0.y * inv, a0.z * inv, a0.w * inv,
                    a1.x * inv, a1.y * inv, a1.z * inv, a1.w * inv};
#pragma unroll
    for (int uu = 0; uu < 8; uu++) {
        float t = val[uu] + b1s[h * 8 + uu];
        val[uu] = t > 0.f ? t : (__expf(t) - 1.f);
    }
    // partial @W2 over my 8 channels
    float part[NCLS];
#pragma unroll
    for (int j = 0; j < NCLS; j++) part[j] = 0.f;
#pragma unroll
    for (int uu = 0; uu < 8; uu++) {
        const float* wrow = &W2s[(h * 8 + uu) * NCLS];
#pragma unroll
        for (int j = 0; j < NCLS; j++) part[j] += val[uu] * wrow[j];
    }
    // reduce across the 8 lanes of this dst (lane bits 0..2 = h)
#pragma unroll
    for (int o = 1; o < 8; o <<= 1)
#pragma unroll
        for (int j = 0; j < NCLS; j++)
            part[j] += __shfl_xor_sync(0xFFFFFFFF, part[j], o);

    // writes: h=0/1 -> h2 halves, h=2 -> as2 table, h=3 -> ad2 table
    if (h < 2) {
        uint4 o4;
        __half2 ph;
        ph = __floats2half2_rn(part[h * 8 + 0], part[h * 8 + 1]); o4.x = *(uint32_t*)&ph;
        ph = __floats2half2_rn(part[h * 8 + 2], part[h * 8 + 3]); o4.y = *(uint32_t*)&ph;
        ph = __floats2half2_rn(part[h * 8 + 4], part[h * 8 + 5]); o4.z = *(uint32_t*)&ph;
        ph = __floats2half2_rn(part[h * 8 + 6], part[h * 8 + 7]); o4.w = *(uint32_t*)&ph;
        *(uint4*)(g_h2h + (size_t)dst * NCLS + h * 8) = o4;
    } else if (h == 2) {
        float as = 0.f;
#pragma unroll
        for (int j = 0; j < NCLS; j++) as += part[j] * s2[j];
        g_as2e[dst] = __floats2half2_rn(__expf(as), __expf(0.2f * as));
    } else if (h == 3) {
        float ad = 0.f;
#pragma unroll
        for (int j = 0; j < NCLS; j++) ad += part[j] * d2[j];
        g_ad2e[dst] = __floats2half2_rn(__expf(ad), __expf(0.2f * ad));
    }
}

// ---------------- layer 2 gather: agg + softmax + bias (4 thr/dst) --------
__global__ __launch_bounds__(256) void gather2_kernel(int N, const float* __restrict__ b2,
                                                      float* __restrict__ out) {
    int gid = blockIdx.x * blockDim.x + threadIdx.x;
    int dst = gid >> 2;
    int t   = gid & 3;
    if (dst >= N) return;
    float2 da = __half22float2(g_ad2e[dst]);
    float4 bv = *(const float4*)(b2 + t * 4);
    int beg = g_off[dst];
    int end = g_cursor[dst];
    float4 a = make_float4(0.f, 0.f, 0.f, 0.f);
    float denom = 0.f;
    int src = g_csr[beg];
    __half2 sah = g_as2e[src];
    uint2 u = *(const uint2*)(g_h2h + (size_t)src * NCLS + t * 4);
    for (int i = beg; i < end; i++) {
        int nsrc = (i + 1 < end) ? g_csr[i + 1] : src;
        __half2 nsah = g_as2e[nsrc];
        uint2 nu = *(const uint2*)(g_h2h + (size_t)nsrc * NCLS + t * 4);
        float2 sa = __half22float2(sah);
        float w = fmaxf(sa.x * da.x, sa.y * da.y);
        float2 p0 = __half22float2(*(__half2*)&u.x);
        float2 p1 = __half22float2(*(__half2*)&u.y);
        a.x += w * p0.x; a.y += w * p0.y; a.z += w * p1.x; a.w += w * p1.y;
        denom += w;
        sah = nsah; u = nu; src = nsrc;
    }
    float inv = 1.f / denom;
    *(float4*)(out + (size_t)dst * NCLS + t * 4) =
        make_float4(a.x * inv + bv.x, a.y * inv + bv.y,
                    a.z * inv + bv.z, a.w * inv + bv.w);
}

// ---------------------------------------------------------------------------
extern "C" void kernel_launch(void* const* d_in, const int* in_sizes, int n_in,
                              void* d_out, int out_size) {
    const float* x        = (const float*)d_in[0];
    const void*  ei       = d_in[1];
    const float* W1       = (const float*)d_in[2];
    const float* att_src1 = (const float*)d_in[3];
    const float* att_dst1 = (const float*)d_in[4];
    const float* b1       = (const float*)d_in[5];
    const float* W2       = (const float*)d_in[6];
    const float* att_src2 = (const float*)d_in[7];
    const float* att_dst2 = (const float*)d_in[8];
    const float* b2       = (const float*)d_in[9];
    float* out = (float*)d_out;

    int N = in_sizes[0] / FIN;       // 100000
    int E = in_sizes[1] / 2;         // 3200000
    int T = E + N;
    int nb = (N + SCAN_BS - 1) / SCAN_BS;

    setup_kernel<<<(N + 255) / 256, 256>>>((const int*)ei, N);
    hist_kernel<<<(T + 255) / 256, 256>>>(ei, E, N);
    scan_kernel<<<nb, SCAN_BS>>>(N);
    scatter_kernel<<<(T + 255) / 256, 256>>>(ei, E, N);
    gemm1_kernel<<<(N + GBM - 1) / GBM, 128>>>(x, W1, att_src1, att_dst1, N);
    gather1_kernel<<<((long long)N * 8 + 255) / 256, 256>>>(N, W2, att_src2, att_dst2, b1);
    gather2_kernel<<<((long long)N * 4 + 255) / 256, 256>>>(N, b2, out);
}